// round 5
// baseline (speedup 1.0000x reference)
#include <cuda_runtime.h>
#include <cuda_bf16.h>
#include <cstdint>

// Problem dims (fixed by the dataset)
#define BB 4
#define TT 256
#define UU 128
#define HH 512
#define VV 1024
#define MM (BB * TT * UU)   // 131072

// ---------------- scratch (module-load allocated) ----------------
__device__ float g_e[BB * TT * HH];                    // 2 MB
__device__ float g_d[BB * UU * HH];                    // 1 MB
// A int8 fragments: [fm (8192)][fk (16)][lane (32)] x 16B  (67 MB each)
__device__ uint4 g_Ahi[(size_t)(MM / 16) * (HH / 32) * 32];
__device__ uint4 g_Alo[(size_t)(MM / 16) * (HH / 32) * 32];
// B int8 fragments: [fn (128)][fk (16)][lane (32)] x 8B    (512 KB each)
__device__ uint2 g_Bhi[(VV / 8) * (HH / 32) * 32];
__device__ uint2 g_Blo[(VV / 8) * (HH / 32) * 32];

// Quantization scales: SB = 1/sqrt(512) strict bound on |W_joint|
#define SB_INV127 2873.6819587421157   // 127/SB = 127*sqrt(512)

// ---------------- helpers ----------------
__device__ __forceinline__ float tanh_apx(float x) {
    float y;
    asm("tanh.approx.f32 %0, %1;" : "=f"(y) : "f"(x));
    return y;
}
__device__ __forceinline__ unsigned long long ffma2(unsigned long long a,
                                                    unsigned long long b,
                                                    unsigned long long c) {
    unsigned long long d;
    asm("fma.rn.f32x2 %0, %1, %2, %3;" : "=l"(d) : "l"(a), "l"(b), "l"(c));
    return d;
}
__device__ __forceinline__ unsigned long long pack2(float lo, float hi) {
    unsigned long long r;
    asm("mov.b64 %0, {%1, %2};" : "=l"(r) : "f"(lo), "f"(hi));
    return r;
}
__device__ __forceinline__ float2 unpack2(unsigned long long v) {
    float2 r;
    asm("mov.b64 {%0, %1}, %2;" : "=f"(r.x), "=f"(r.y) : "l"(v));
    return r;
}
__device__ __forceinline__ uint32_t bpack4(int a, int b, int c, int d) {
    return (uint32_t)(a & 255) | ((uint32_t)(b & 255) << 8) |
           ((uint32_t)(c & 255) << 16) | ((uint32_t)(d & 255) << 24);
}
// two-level int8 quantization of x*scale: h = rint(f), l = rint((f-h)*127)
__device__ __forceinline__ void quant2(float x, float scale, int& h, int& l) {
    float f = x * scale;
    h = __float2int_rn(f);
    l = __float2int_rn((f - (float)h) * 127.0f);
}
// m16n8k32 row.col s8 -> s32 accumulate (baseline PTX, sm_80+)
__device__ __forceinline__ void imma16832(int* c, const uint32_t* a,
                                          const uint32_t* b) {
    asm volatile(
        "mma.sync.aligned.m16n8k32.row.col.s32.s8.s8.s32 "
        "{%0,%1,%2,%3}, {%4,%5,%6,%7}, {%8,%9}, {%0,%1,%2,%3};"
        : "+r"(c[0]), "+r"(c[1]), "+r"(c[2]), "+r"(c[3])
        : "r"(a[0]), "r"(a[1]), "r"(a[2]), "r"(a[3]), "r"(b[0]), "r"(b[1]));
}

// ---------------- small fp32 SGEMM (projections, proven) ----------------
__global__ __launch_bounds__(256, 2) void sgemm_bias(
    const float* __restrict__ A, const float* __restrict__ W,
    const float* __restrict__ bias, float* __restrict__ C,
    int M, int N, int K)
{
    __shared__ float As[16][132];
    __shared__ float Bs[16][132];

    const int t = threadIdx.x;
    const int nBase = blockIdx.x * 128;
    const int mBase = blockIdx.y * 128;
    const int m0 = (t >> 4) * 4;
    const int n0 = (t & 15) * 4;
    const int lrow = t >> 2;
    const int lcol = (t & 3) * 4;

    unsigned long long acc[8][4];
#pragma unroll
    for (int i = 0; i < 8; i++)
#pragma unroll
        for (int jj = 0; jj < 4; jj++) acc[i][jj] = 0ULL;

    const float* Aptr0 = A + (size_t)(mBase + lrow) * K + lcol;
    const float* Aptr1 = A + (size_t)(mBase + lrow + 64) * K + lcol;
    const float* Wptr0 = W + (size_t)(nBase + lrow) * K + lcol;
    const float* Wptr1 = W + (size_t)(nBase + lrow + 64) * K + lcol;

    for (int k0 = 0; k0 < K; k0 += 16) {
        float4 a0 = *(const float4*)(Aptr0 + k0);
        float4 a1 = *(const float4*)(Aptr1 + k0);
        float4 b0 = *(const float4*)(Wptr0 + k0);
        float4 b1 = *(const float4*)(Wptr1 + k0);
        __syncthreads();
        As[lcol + 0][lrow] = a0.x; As[lcol + 1][lrow] = a0.y;
        As[lcol + 2][lrow] = a0.z; As[lcol + 3][lrow] = a0.w;
        As[lcol + 0][lrow + 64] = a1.x; As[lcol + 1][lrow + 64] = a1.y;
        As[lcol + 2][lrow + 64] = a1.z; As[lcol + 3][lrow + 64] = a1.w;
        Bs[lcol + 0][lrow] = b0.x; Bs[lcol + 1][lrow] = b0.y;
        Bs[lcol + 2][lrow] = b0.z; Bs[lcol + 3][lrow] = b0.w;
        Bs[lcol + 0][lrow + 64] = b1.x; Bs[lcol + 1][lrow + 64] = b1.y;
        Bs[lcol + 2][lrow + 64] = b1.z; Bs[lcol + 3][lrow + 64] = b1.w;
        __syncthreads();

#pragma unroll
        for (int k = 0; k < 16; k++) {
            float4 av0 = *(const float4*)&As[k][m0];
            float4 av1 = *(const float4*)&As[k][m0 + 64];
            float4 bv0 = *(const float4*)&Bs[k][n0];
            float4 bv1 = *(const float4*)&Bs[k][n0 + 64];
            unsigned long long bp[4];
            bp[0] = pack2(bv0.x, bv0.y);
            bp[1] = pack2(bv0.z, bv0.w);
            bp[2] = pack2(bv1.x, bv1.y);
            bp[3] = pack2(bv1.z, bv1.w);
            float am[8] = {av0.x, av0.y, av0.z, av0.w,
                           av1.x, av1.y, av1.z, av1.w};
#pragma unroll
            for (int i = 0; i < 8; i++) {
                unsigned long long ad = pack2(am[i], am[i]);
#pragma unroll
                for (int jj = 0; jj < 4; jj++)
                    acc[i][jj] = ffma2(ad, bp[jj], acc[i][jj]);
            }
        }
    }

    float4 bias0 = *(const float4*)(bias + nBase + n0);
    float4 bias1 = *(const float4*)(bias + nBase + n0 + 64);
#pragma unroll
    for (int i = 0; i < 8; i++) {
        const int mg = mBase + m0 + ((i < 4) ? i : (i + 60));
        float2 p0 = unpack2(acc[i][0]);
        float2 p1 = unpack2(acc[i][1]);
        float2 p2 = unpack2(acc[i][2]);
        float2 p3 = unpack2(acc[i][3]);
        float4 o0 = make_float4(p0.x + bias0.x, p0.y + bias0.y,
                                p1.x + bias0.z, p1.y + bias0.w);
        float4 o1 = make_float4(p2.x + bias1.x, p2.y + bias1.y,
                                p3.x + bias1.z, p3.y + bias1.w);
        float* crow = C + (size_t)mg * N + nBase;
        *(float4*)(crow + n0) = o0;
        *(float4*)(crow + n0 + 64) = o1;
    }
}

// ---------------- pack W -> int8 hi/lo B-fragments (m16n8k32 col) --------
// lane l: n = fn*8 + (l>>2); k0 = fk*32 + (l&3)*4
// b0 bytes = W[n][k0..k0+3], b1 bytes = W[n][k0+16..k0+19]
__global__ __launch_bounds__(256) void pack_b(
    const float* __restrict__ W, uint2* __restrict__ Bhi, uint2* __restrict__ Blo)
{
    const int gid = blockIdx.x * 256 + threadIdx.x;  // < 65536
    const int lane = gid & 31;
    const int fk = (gid >> 5) & 15;
    const int fn = gid >> 9;

    const int n = fn * 8 + (lane >> 2);
    const int k0 = fk * 32 + (lane & 3) * 4;
    const float* wr = W + (size_t)n * HH;
    float4 w0 = *(const float4*)(wr + k0);
    float4 w1 = *(const float4*)(wr + k0 + 16);

    const float c1 = (float)SB_INV127;
    int h[8], l[8];
    quant2(w0.x, c1, h[0], l[0]); quant2(w0.y, c1, h[1], l[1]);
    quant2(w0.z, c1, h[2], l[2]); quant2(w0.w, c1, h[3], l[3]);
    quant2(w1.x, c1, h[4], l[4]); quant2(w1.y, c1, h[5], l[5]);
    quant2(w1.z, c1, h[6], l[6]); quant2(w1.w, c1, h[7], l[7]);

    Bhi[gid] = make_uint2(bpack4(h[0], h[1], h[2], h[3]),
                          bpack4(h[4], h[5], h[6], h[7]));
    Blo[gid] = make_uint2(bpack4(l[0], l[1], l[2], l[3]),
                          bpack4(l[4], l[5], l[6], l[7]));
}

// ---------------- pack A = tanh(e (+) d) -> int8 hi/lo A-fragments -------
// m16n8k32 row: lane l: g = l>>2; k0 = fk*32 + (l&3)*4
// a0 = row g  k[k0..k0+3]; a1 = row g+8 same k; a2 = row g k0+16..; a3 = row g+8
__global__ __launch_bounds__(256) void pack_a(
    const float* __restrict__ e, const float* __restrict__ dmat,
    uint4* __restrict__ Ahi, uint4* __restrict__ Alo)
{
    const int gid = blockIdx.x * 256 + threadIdx.x;  // < 4194304
    const int lane = gid & 31;
    const int fk = (gid >> 5) & 15;
    const int fm = gid >> 9;                          // < 8192

    const int g = lane >> 2;
    const int k0 = fk * 32 + (lane & 3) * 4;
    const int m0 = fm * 16 + g;
    const int bt = m0 >> 7;
    const int u0 = m0 & 127;   // rows m0, m0+8 share bt (16-aligned block)
    const int b = bt >> 8;

    const float* erow = e + (size_t)bt * HH;
    const float* dr0 = dmat + (size_t)(b * 128 + u0) * HH;
    const float* dr1 = dr0 + 8 * HH;

    float4 e0 = *(const float4*)(erow + k0);
    float4 e1 = *(const float4*)(erow + k0 + 16);
    float4 x0 = *(const float4*)(dr0 + k0);
    float4 x1 = *(const float4*)(dr0 + k0 + 16);
    float4 y0 = *(const float4*)(dr1 + k0);
    float4 y1 = *(const float4*)(dr1 + k0 + 16);

    int h[16], l[16];
    // row g, k0..k0+3 -> a0 ; row g, k0+16.. -> a2
    quant2(tanh_apx(e0.x + x0.x), 127.f, h[0], l[0]);
    quant2(tanh_apx(e0.y + x0.y), 127.f, h[1], l[1]);
    quant2(tanh_apx(e0.z + x0.z), 127.f, h[2], l[2]);
    quant2(tanh_apx(e0.w + x0.w), 127.f, h[3], l[3]);
    quant2(tanh_apx(e1.x + x1.x), 127.f, h[8], l[8]);
    quant2(tanh_apx(e1.y + x1.y), 127.f, h[9], l[9]);
    quant2(tanh_apx(e1.z + x1.z), 127.f, h[10], l[10]);
    quant2(tanh_apx(e1.w + x1.w), 127.f, h[11], l[11]);
    // row g+8 -> a1, a3
    quant2(tanh_apx(e0.x + y0.x), 127.f, h[4], l[4]);
    quant2(tanh_apx(e0.y + y0.y), 127.f, h[5], l[5]);
    quant2(tanh_apx(e0.z + y0.z), 127.f, h[6], l[6]);
    quant2(tanh_apx(e0.w + y0.w), 127.f, h[7], l[7]);
    quant2(tanh_apx(e1.x + y1.x), 127.f, h[12], l[12]);
    quant2(tanh_apx(e1.y + y1.y), 127.f, h[13], l[13]);
    quant2(tanh_apx(e1.z + y1.z), 127.f, h[14], l[14]);
    quant2(tanh_apx(e1.w + y1.w), 127.f, h[15], l[15]);

    Ahi[gid] = make_uint4(bpack4(h[0], h[1], h[2], h[3]),
                          bpack4(h[4], h[5], h[6], h[7]),
                          bpack4(h[8], h[9], h[10], h[11]),
                          bpack4(h[12], h[13], h[14], h[15]));
    Alo[gid] = make_uint4(bpack4(l[0], l[1], l[2], l[3]),
                          bpack4(l[4], l[5], l[6], l[7]),
                          bpack4(l[8], l[9], l[10], l[11]),
                          bpack4(l[12], l[13], l[14], l[15]));
}

// ---------------- joint GEMM: IMMA 3-pass, dual s32 accumulators ----------
// CTA 128x128, 8 warps (2M x 4N), warp tile 64x32 = 4x4 (m16n8) frags.
__global__ __launch_bounds__(256) void joint_gemm(
    const uint4* __restrict__ Ahi, const uint4* __restrict__ Alo,
    const uint2* __restrict__ Bhi, const uint2* __restrict__ Blo,
    const float* __restrict__ bias, float* __restrict__ out)
{
    const int tid = threadIdx.x;
    const int lane = tid & 31;
    const int wid = tid >> 5;
    const int wr = wid >> 2;
    const int wc = wid & 3;
    const int mt = blockIdx.y;          // 0..1023
    const int nt = blockIdx.x;          // 0..7

    const int fmBase = mt * 8 + wr * 4;
    const int fnBase = nt * 16 + wc * 4;

    int cm[4][4][4], cc[4][4][4];
#pragma unroll
    for (int i = 0; i < 4; i++)
#pragma unroll
        for (int j = 0; j < 4; j++)
#pragma unroll
            for (int q = 0; q < 4; q++) { cm[i][j][q] = 0; cc[i][j][q] = 0; }

    for (int fk = 0; fk < 16; fk++) {
        uint4 ah[4], al[4];
        uint2 bh[4], bl[4];
#pragma unroll
        for (int i = 0; i < 4; i++) {
            const size_t idx = ((size_t)(fmBase + i) * 16 + fk) * 32 + lane;
            ah[i] = __ldg(Ahi + idx);
            al[i] = __ldg(Alo + idx);
        }
#pragma unroll
        for (int j = 0; j < 4; j++) {
            const size_t idx = ((size_t)(fnBase + j) * 16 + fk) * 32 + lane;
            bh[j] = __ldg(Bhi + idx);
            bl[j] = __ldg(Blo + idx);
        }
        // main: Ah*Bh -> cm
#pragma unroll
        for (int i = 0; i < 4; i++)
#pragma unroll
            for (int j = 0; j < 4; j++)
                imma16832(cm[i][j], (const uint32_t*)&ah[i], (const uint32_t*)&bh[j]);
        // cross: Ah*Bl + Al*Bh -> cc (shared scale)
#pragma unroll
        for (int i = 0; i < 4; i++)
#pragma unroll
            for (int j = 0; j < 4; j++)
                imma16832(cc[i][j], (const uint32_t*)&ah[i], (const uint32_t*)&bl[j]);
#pragma unroll
        for (int i = 0; i < 4; i++)
#pragma unroll
            for (int j = 0; j < 4; j++)
                imma16832(cc[i][j], (const uint32_t*)&al[i], (const uint32_t*)&bh[j]);
    }

    // epilogue: out = S1*cm + S2*cc + bias
    const float S1 = (float)(0.044194173824159216 / 16129.0);
    const float S2 = (float)(0.044194173824159216 / 16129.0 / 127.0);
    const int g = lane >> 2;
    const int t2 = (lane & 3) * 2;
#pragma unroll
    for (int j = 0; j < 4; j++) {
        const int col = nt * 128 + wc * 32 + j * 8 + t2;
        const float2 bv = *(const float2*)(bias + col);
#pragma unroll
        for (int i = 0; i < 4; i++) {
            const int row = mt * 128 + wr * 64 + i * 16 + g;
            float2 o0, o1;
            o0.x = __int2float_rn(cm[i][j][0]) * S1 + __int2float_rn(cc[i][j][0]) * S2 + bv.x;
            o0.y = __int2float_rn(cm[i][j][1]) * S1 + __int2float_rn(cc[i][j][1]) * S2 + bv.y;
            o1.x = __int2float_rn(cm[i][j][2]) * S1 + __int2float_rn(cc[i][j][2]) * S2 + bv.x;
            o1.y = __int2float_rn(cm[i][j][3]) * S1 + __int2float_rn(cc[i][j][3]) * S2 + bv.y;
            *(float2*)(out + (size_t)row * VV + col) = o0;
            *(float2*)(out + (size_t)(row + 8) * VV + col) = o1;
        }
    }
}

// ---------------- launch ----------------
extern "C" void kernel_launch(void* const* d_in, const int* in_sizes, int n_in,
                              void* d_out, int out_size)
{
    const float* enc     = (const float*)d_in[0];
    const float* dec     = (const float*)d_in[1];
    const float* W_enc   = (const float*)d_in[2];
    const float* b_enc   = (const float*)d_in[3];
    const float* W_dec   = (const float*)d_in[4];
    const float* b_dec   = (const float*)d_in[5];
    const float* W_joint = (const float*)d_in[6];
    const float* b_joint = (const float*)d_in[7];
    float* out = (float*)d_out;

    float *e_ptr, *d_ptr;
    uint4 *ahi, *alo;
    uint2 *bhi, *blo;
    cudaGetSymbolAddress((void**)&e_ptr, g_e);
    cudaGetSymbolAddress((void**)&d_ptr, g_d);
    cudaGetSymbolAddress((void**)&ahi, g_Ahi);
    cudaGetSymbolAddress((void**)&alo, g_Alo);
    cudaGetSymbolAddress((void**)&bhi, g_Bhi);
    cudaGetSymbolAddress((void**)&blo, g_Blo);

    // W_joint -> int8 fragment-ordered hi/lo
    pack_b<<<(VV / 8) * (HH / 32) * 32 / 256, 256>>>(W_joint, bhi, blo);
    // projections (fp32)
    sgemm_bias<<<dim3(4, 8), 256>>>(enc, W_enc, b_enc, e_ptr, BB * TT, HH, HH);
    sgemm_bias<<<dim3(4, 4), 256>>>(dec, W_dec, b_dec, d_ptr, BB * UU, HH, HH);
    // A = tanh(e (+) d) -> int8 fragment-ordered hi/lo
    pack_a<<<(MM / 16) * (HH / 32) * 32 / 256, 256>>>(e_ptr, d_ptr, ahi, alo);
    // out = A @ W^T + bias (IMMA 3-pass)
    joint_gemm<<<dim3(VV / 128, MM / 128), 256>>>(ahi, alo, bhi, blo, b_joint, out);
}

// round 6
// speedup vs baseline: 6.7639x; 6.7639x over previous
#include <cuda_runtime.h>
#include <cuda_fp16.h>
#include <cstdint>

// Problem dims (fixed by the dataset)
#define BB 4
#define TT 256
#define UU 128
#define HH 512
#define VV 1024
#define MM (BB * TT * UU)   // 131072

// ---------------- scratch (module-load allocated) ----------------
__device__ float g_e[BB * TT * HH];                    // 2 MB
__device__ float g_d[BB * UU * HH];                    // 1 MB
// A fp16 fragments: [fm (8192)][fk (32)][lane (32)] x 16B  (134 MB)
__device__ uint4 g_Af[(size_t)(MM / 16) * (HH / 16) * 32];
// B fp16 fragments: [fn (128)][fk (32)][lane (32)] x 8B    (1 MB)
__device__ uint2 g_Bf[(VV / 8) * (HH / 16) * 32];

// ---------------- helpers ----------------
__device__ __forceinline__ float tanh_apx(float x) {
    float y;
    asm("tanh.approx.f32 %0, %1;" : "=f"(y) : "f"(x));
    return y;
}
// pack {lower = a, upper = b} as f16x2
__device__ __forceinline__ uint32_t cvt_f16x2(float a_low, float b_high) {
    uint32_t r;
    asm("cvt.rn.f16x2.f32 %0, %1, %2;" : "=r"(r) : "f"(b_high), "f"(a_low));
    return r;
}
__device__ __forceinline__ unsigned long long ffma2(unsigned long long a,
                                                    unsigned long long b,
                                                    unsigned long long c) {
    unsigned long long d;
    asm("fma.rn.f32x2 %0, %1, %2, %3;" : "=l"(d) : "l"(a), "l"(b), "l"(c));
    return d;
}
__device__ __forceinline__ unsigned long long pack2(float lo, float hi) {
    unsigned long long r;
    asm("mov.b64 %0, {%1, %2};" : "=l"(r) : "f"(lo), "f"(hi));
    return r;
}
__device__ __forceinline__ float2 unpack2(unsigned long long v) {
    float2 r;
    asm("mov.b64 {%0, %1}, %2;" : "=f"(r.x), "=f"(r.y) : "l"(v));
    return r;
}
// m16n8k16 row.col fp16 -> f32 accumulate (baseline PTX, sm_80+)
__device__ __forceinline__ void mma16816(float* c, const uint32_t* a,
                                         const uint32_t* b) {
    asm volatile(
        "mma.sync.aligned.m16n8k16.row.col.f32.f16.f16.f32 "
        "{%0,%1,%2,%3}, {%4,%5,%6,%7}, {%8,%9}, {%0,%1,%2,%3};"
        : "+f"(c[0]), "+f"(c[1]), "+f"(c[2]), "+f"(c[3])
        : "r"(a[0]), "r"(a[1]), "r"(a[2]), "r"(a[3]), "r"(b[0]), "r"(b[1]));
}

// ---------------- small fp32 SGEMM (projections, proven) ----------------
__global__ __launch_bounds__(256, 2) void sgemm_bias(
    const float* __restrict__ A, const float* __restrict__ W,
    const float* __restrict__ bias, float* __restrict__ C,
    int M, int N, int K)
{
    __shared__ float As[16][132];
    __shared__ float Bs[16][132];

    const int t = threadIdx.x;
    const int nBase = blockIdx.x * 128;
    const int mBase = blockIdx.y * 128;
    const int m0 = (t >> 4) * 4;
    const int n0 = (t & 15) * 4;
    const int lrow = t >> 2;
    const int lcol = (t & 3) * 4;

    unsigned long long acc[8][4];
#pragma unroll
    for (int i = 0; i < 8; i++)
#pragma unroll
        for (int jj = 0; jj < 4; jj++) acc[i][jj] = 0ULL;

    const float* Aptr0 = A + (size_t)(mBase + lrow) * K + lcol;
    const float* Aptr1 = A + (size_t)(mBase + lrow + 64) * K + lcol;
    const float* Wptr0 = W + (size_t)(nBase + lrow) * K + lcol;
    const float* Wptr1 = W + (size_t)(nBase + lrow + 64) * K + lcol;

    for (int k0 = 0; k0 < K; k0 += 16) {
        float4 a0 = *(const float4*)(Aptr0 + k0);
        float4 a1 = *(const float4*)(Aptr1 + k0);
        float4 b0 = *(const float4*)(Wptr0 + k0);
        float4 b1 = *(const float4*)(Wptr1 + k0);
        __syncthreads();
        As[lcol + 0][lrow] = a0.x; As[lcol + 1][lrow] = a0.y;
        As[lcol + 2][lrow] = a0.z; As[lcol + 3][lrow] = a0.w;
        As[lcol + 0][lrow + 64] = a1.x; As[lcol + 1][lrow + 64] = a1.y;
        As[lcol + 2][lrow + 64] = a1.z; As[lcol + 3][lrow + 64] = a1.w;
        Bs[lcol + 0][lrow] = b0.x; Bs[lcol + 1][lrow] = b0.y;
        Bs[lcol + 2][lrow] = b0.z; Bs[lcol + 3][lrow] = b0.w;
        Bs[lcol + 0][lrow + 64] = b1.x; Bs[lcol + 1][lrow + 64] = b1.y;
        Bs[lcol + 2][lrow + 64] = b1.z; Bs[lcol + 3][lrow + 64] = b1.w;
        __syncthreads();

#pragma unroll
        for (int k = 0; k < 16; k++) {
            float4 av0 = *(const float4*)&As[k][m0];
            float4 av1 = *(const float4*)&As[k][m0 + 64];
            float4 bv0 = *(const float4*)&Bs[k][n0];
            float4 bv1 = *(const float4*)&Bs[k][n0 + 64];
            unsigned long long bp[4];
            bp[0] = pack2(bv0.x, bv0.y);
            bp[1] = pack2(bv0.z, bv0.w);
            bp[2] = pack2(bv1.x, bv1.y);
            bp[3] = pack2(bv1.z, bv1.w);
            float am[8] = {av0.x, av0.y, av0.z, av0.w,
                           av1.x, av1.y, av1.z, av1.w};
#pragma unroll
            for (int i = 0; i < 8; i++) {
                unsigned long long ad = pack2(am[i], am[i]);
#pragma unroll
                for (int jj = 0; jj < 4; jj++)
                    acc[i][jj] = ffma2(ad, bp[jj], acc[i][jj]);
            }
        }
    }

    float4 bias0 = *(const float4*)(bias + nBase + n0);
    float4 bias1 = *(const float4*)(bias + nBase + n0 + 64);
#pragma unroll
    for (int i = 0; i < 8; i++) {
        const int mg = mBase + m0 + ((i < 4) ? i : (i + 60));
        float2 p0 = unpack2(acc[i][0]);
        float2 p1 = unpack2(acc[i][1]);
        float2 p2 = unpack2(acc[i][2]);
        float2 p3 = unpack2(acc[i][3]);
        float4 o0 = make_float4(p0.x + bias0.x, p0.y + bias0.y,
                                p1.x + bias0.z, p1.y + bias0.w);
        float4 o1 = make_float4(p2.x + bias1.x, p2.y + bias1.y,
                                p3.x + bias1.z, p3.y + bias1.w);
        float* crow = C + (size_t)mg * N + nBase;
        *(float4*)(crow + n0) = o0;
        *(float4*)(crow + n0 + 64) = o1;
    }
}

// ---------------- pack W -> fp16 B-fragments (m16n8k16 col) ----------------
// lane l: n = fn*8 + (l>>2), k0 = fk*16 + 2*(l&3)
// regs: {W[n][k0],W[n][k0+1]} , {W[n][k0+8],W[n][k0+9]}
__global__ __launch_bounds__(256) void pack_b(
    const float* __restrict__ W, uint2* __restrict__ Bf)
{
    const int gid = blockIdx.x * 256 + threadIdx.x;  // < 131072
    const int lane = gid & 31;
    const int fk = (gid >> 5) & 31;
    const int fn = gid >> 10;

    const int n = fn * 8 + (lane >> 2);
    const int k0 = fk * 16 + (lane & 3) * 2;
    const float* wr = W + (size_t)n * HH;
    float2 w01 = *(const float2*)(wr + k0);
    float2 w89 = *(const float2*)(wr + k0 + 8);

    Bf[gid] = make_uint2(cvt_f16x2(w01.x, w01.y), cvt_f16x2(w89.x, w89.y));
}

// ---------------- pack A = tanh(e (+) d) -> fp16 A-fragments ----------------
// m16n8k16 row: lane l: g = l>>2, k0 = fk*16 + 2*(l&3)
// regs: {A[g][k0..]}, {A[g+8][k0..]}, {A[g][k0+8..]}, {A[g+8][k0+8..]}
__global__ __launch_bounds__(256) void pack_a(
    const float* __restrict__ e, const float* __restrict__ dmat,
    uint4* __restrict__ Af)
{
    const int gid = blockIdx.x * 256 + threadIdx.x;  // < 8388608
    const int lane = gid & 31;
    const int fk = (gid >> 5) & 31;
    const int fm = gid >> 10;                         // < 8192

    const int g = lane >> 2;
    const int k0 = fk * 16 + (lane & 3) * 2;
    const int m0 = fm * 16 + g;
    const int bt = m0 >> 7;
    const int u0 = m0 & 127;      // rows m0, m0+8 share bt (16-aligned block)
    const int b = bt >> 8;

    const float* erow = e + (size_t)bt * HH;
    const float* dr0 = dmat + (size_t)(b * 128 + u0) * HH;
    const float* dr1 = dr0 + 8 * HH;

    float2 e01 = *(const float2*)(erow + k0);
    float2 e89 = *(const float2*)(erow + k0 + 8);
    float2 d001 = *(const float2*)(dr0 + k0);
    float2 d089 = *(const float2*)(dr0 + k0 + 8);
    float2 d101 = *(const float2*)(dr1 + k0);
    float2 d189 = *(const float2*)(dr1 + k0 + 8);

    float x0 = tanh_apx(e01.x + d001.x), x1 = tanh_apx(e01.y + d001.y);
    float x8 = tanh_apx(e89.x + d089.x), x9 = tanh_apx(e89.y + d089.y);
    float y0 = tanh_apx(e01.x + d101.x), y1 = tanh_apx(e01.y + d101.y);
    float y8 = tanh_apx(e89.x + d189.x), y9 = tanh_apx(e89.y + d189.y);

    Af[gid] = make_uint4(cvt_f16x2(x0, x1), cvt_f16x2(y0, y1),
                         cvt_f16x2(x8, x9), cvt_f16x2(y8, y9));
}

// ---------------- joint GEMM: out = A @ W^T + bias, single-pass HMMA ------
// CTA 128x128, 8 warps as 2(M) x 4(N); warp tile 64x32.
__global__ __launch_bounds__(256, 2) void joint_gemm(
    const uint4* __restrict__ Af, const uint2* __restrict__ Bf,
    const float* __restrict__ bias, float* __restrict__ out)
{
    const int tid = threadIdx.x;
    const int lane = tid & 31;
    const int wid = tid >> 5;
    const int wr = wid >> 2;            // 0..1  (64-row block)
    const int wc = wid & 3;             // 0..3  (32-col block)
    const int mt = blockIdx.y;          // 0..1023
    const int nt = blockIdx.x;          // 0..7

    const int fmBase = mt * 8 + wr * 4;
    const int fnBase = nt * 16 + wc * 4;

    float c[4][4][4];
#pragma unroll
    for (int i = 0; i < 4; i++)
#pragma unroll
        for (int j = 0; j < 4; j++)
#pragma unroll
            for (int q = 0; q < 4; q++) c[i][j][q] = 0.f;

    for (int fk = 0; fk < 32; fk++) {
        uint4 a[4];
        uint2 b[4];
#pragma unroll
        for (int i = 0; i < 4; i++) {
            const size_t idx = ((size_t)(fmBase + i) * 32 + fk) * 32 + lane;
            a[i] = __ldg(Af + idx);
        }
#pragma unroll
        for (int j = 0; j < 4; j++) {
            const size_t idx = ((size_t)(fnBase + j) * 32 + fk) * 32 + lane;
            b[j] = __ldg(Bf + idx);
        }
#pragma unroll
        for (int i = 0; i < 4; i++)
#pragma unroll
            for (int j = 0; j < 4; j++)
                mma16816(c[i][j], (const uint32_t*)&a[i], (const uint32_t*)&b[j]);
    }

    // epilogue: C frag lane mapping: rows g, g+8 ; cols 2t, 2t+1
    const int g = lane >> 2;
    const int t2 = (lane & 3) * 2;
#pragma unroll
    for (int j = 0; j < 4; j++) {
        const int col = nt * 128 + wc * 32 + j * 8 + t2;
        const float2 bv = *(const float2*)(bias + col);
#pragma unroll
        for (int i = 0; i < 4; i++) {
            const int row = mt * 128 + wr * 64 + i * 16 + g;
            float2 o0 = make_float2(c[i][j][0] + bv.x, c[i][j][1] + bv.y);
            float2 o1 = make_float2(c[i][j][2] + bv.x, c[i][j][3] + bv.y);
            *(float2*)(out + (size_t)row * VV + col) = o0;
            *(float2*)(out + (size_t)(row + 8) * VV + col) = o1;
        }
    }
}

// ---------------- launch ----------------
extern "C" void kernel_launch(void* const* d_in, const int* in_sizes, int n_in,
                              void* d_out, int out_size)
{
    const float* enc     = (const float*)d_in[0];
    const float* dec     = (const float*)d_in[1];
    const float* W_enc   = (const float*)d_in[2];
    const float* b_enc   = (const float*)d_in[3];
    const float* W_dec   = (const float*)d_in[4];
    const float* b_dec   = (const float*)d_in[5];
    const float* W_joint = (const float*)d_in[6];
    const float* b_joint = (const float*)d_in[7];
    float* out = (float*)d_out;

    float *e_ptr, *d_ptr;
    uint4 *af;
    uint2 *bf;
    cudaGetSymbolAddress((void**)&e_ptr, g_e);
    cudaGetSymbolAddress((void**)&d_ptr, g_d);
    cudaGetSymbolAddress((void**)&af, g_Af);
    cudaGetSymbolAddress((void**)&bf, g_Bf);

    // W_joint -> fp16 fragment-ordered
    pack_b<<<(VV / 8) * (HH / 16) * 32 / 256, 256>>>(W_joint, bf);
    // projections (fp32)
    sgemm_bias<<<dim3(4, 8), 256>>>(enc, W_enc, b_enc, e_ptr, BB * TT, HH, HH);
    sgemm_bias<<<dim3(4, 4), 256>>>(dec, W_dec, b_dec, d_ptr, BB * UU, HH, HH);
    // A = tanh(e (+) d) -> fp16 fragment-ordered
    pack_a<<<(MM / 16) * (HH / 16) * 32 / 256, 256>>>(e_ptr, d_ptr, af);
    // out = A @ W^T + bias (single-pass fp16 HMMA)
    joint_gemm<<<dim3(VV / 128, MM / 128), 256>>>(af, bf, b_joint, out);
}